// round 9
// baseline (speedup 1.0000x reference)
#include <cuda_runtime.h>

// RayPointRefiner: inverse-CDF fine sampling + ANALYTIC merge (no sort).
// N_RAYS=524288, N_PTS=64, N_FINE=64, out=[N_RAYS,128] sorted.
//
// One warp per ray; lane l owns cdf intervals 2l, 2l+1.
// u_k = k/63 uniform => searchsorted inverted via thresholds t(c)=min{k: u_k>=c}.
// Interval m owns samples k in [t_m, t_{m+1}) (threshold sequence made globally
// monotone by an integer max-scan => exact tiling). Each sample lies in
// [bins[m], bins[m+1]] which straddles exactly z[m+1], so merged output
// positions are closed-form; everything scatters straight to out[128] shared.

#define EPSF 1e-5f

constexpr int N_RAYS  = 524288;
constexpr int WPB     = 8;
constexpr int THREADS = WPB * 32;
constexpr unsigned FULL = 0xffffffffu;
constexpr float INV63 = 1.0f / 63.0f;

__device__ __forceinline__ float uval(int k) {
    return (k >= 63) ? 1.0f : (float)k * INV63;
}
// exact t(c) = min{k in [0,63] : uval(k) >= c}, c in [0,1]
__device__ __forceinline__ int thresh(float c) {
    int t = (int)ceilf(c * 63.0f);
    t = max(1, min(t, 63));
    if (uval(t - 1) >= c)      t -= 1;
    else if (uval(t) < c)      t += 1;
    return t;
}

__global__ __launch_bounds__(THREADS) void refine_kernel(
    const float* __restrict__ lengths,
    const float* __restrict__ rw,
    float* __restrict__ out_g)
{
    __shared__ __align__(16) float osh[WPB][128];
    const int lane = threadIdx.x & 31;
    const int warp = threadIdx.x >> 5;
    const int ray  = blockIdx.x * WPB + warp;
    float* o = osh[warp];

    // ---- coalesced loads: lane l gets elements 2l, 2l+1 ----
    const float2 za = ((const float2*)lengths)[(size_t)ray * 32 + lane];
    const float2 wa = ((const float2*)rw)     [(size_t)ray * 32 + lane];

    const float znext = __shfl_down_sync(FULL, za.x, 1);
    const float wnext = __shfl_down_sync(FULL, wa.x, 1);

    const float bin0 = 0.5f * (za.x + za.y);             // bins[2l]
    float       bin1 = 0.5f * (za.y + znext);            // bins[2l+1] (lane<31)
    const float binN = __shfl_down_sync(FULL, bin0, 1);  // bins[2l+2] (lane<31)

    // weights w[2l]=rw[2l+1]+eps, w[2l+1]=rw[2l+2]+eps (lanes 0..30)
    float w0 = 0.0f, w1 = 0.0f;
    if (lane < 31) { w0 = wa.y + EPSF; w1 = wnext + EPSF; }

    // inclusive warp scan of pair sums
    float incl = w0 + w1;
    #pragma unroll
    for (int d = 1; d < 32; d <<= 1) {
        float v = __shfl_up_sync(FULL, incl, d);
        if (lane >= d) incl += v;
    }
    float excl = __shfl_up_sync(FULL, incl, 1);
    if (lane == 0) excl = 0.0f;
    const float total = __shfl_sync(FULL, incl, 31);
    const float invW  = 1.0f / total;

    // boundaries: c0=cdf[2l], c1=cdf[2l+1], cB2=cdf[2l+2].
    // c0 (lane l) == cB2 (lane l-1) bit-exactly (both = incl_{l-1}*invW).
    float c0  = fminf(excl * invW, 1.0f);
    float c1  = fminf((excl + w0) * invW, 1.0f);
    float cB2 = fminf(incl * invW, 1.0f);
    if (lane == 30) cB2 = 1.0f;                      // exact top at cdf[62]
    if (lane == 31) { c0 = 1.0f; c1 = 1.0f; bin1 = bin0; }  // degenerate iv 62

    // thresholds (sentinel 64 above interval 62), locally monotone
    int t1 = (lane == 31) ? 64 : thresh(c1);
    int t2 = (lane == 31) ? 64 : thresh(cB2);
    t2 = max(t2, t1);
    // inclusive int max-scan of t2 -> globally monotone boundary indices
    int P = t2;
    #pragma unroll
    for (int d = 1; d < 32; d <<= 1) {
        int v = __shfl_up_sync(FULL, P, d);
        if (lane >= d) P = max(P, v);
    }
    int Pe = __shfl_up_sync(FULL, P, 1);
    if (lane == 0) Pe = 0;
    const int t1f = max(t1, Pe);
    // interval A=2l: k in [Pe, t1f), interval B=2l+1: k in [t1f, P)

    // ---- interval A: bounds (c0,c1), bins (bin0,bin1), straddles za.y ----
    int splitA = 0;
    {
        float d = c1 - c0; if (d < EPSF) d = 1.0f;
        const float r = 1.0f / d;
        const float dbin = bin1 - bin0;
        const int base = 2 * lane + 2;               // (m+1)+1 = 2l+2
        for (int k = Pe; k < t1f; ++k) {
            const float t = (uval(k) - c0) * r;
            const float z = fmaf(t, dbin, bin0);
            const int lt = (z < za.y);
            splitA += lt;
            o[k + base - lt] = z;
        }
    }
    // ---- interval B: bounds (c1,cB2), bins (bin1,binN), straddles znext ----
    int splitB = 0;
    {
        float d = cB2 - c1; if (d < EPSF) d = 1.0f;
        const float r = 1.0f / d;
        const float dbin = binN - bin1;
        const int base = 2 * lane + 3;               // (m+1)+1 = 2l+3
        for (int k = t1f; k < P; ++k) {
            const float t = (uval(k) - c1) * r;
            const float z = fmaf(t, dbin, bin1);
            const int lt = (z < znext);
            splitB += lt;
            o[k + base - lt] = z;
        }
    }

    // ---- coarse z positions: pos(z_i) = i + start(iv i-1) + split(iv i-1) ----
    int prevB = __shfl_up_sync(FULL, t1f + splitB, 1);
    if (lane == 0) prevB = 0;
    o[2 * lane     + prevB]       = za.x;   // i=2l   uses interval 2l-1
    o[2 * lane + 1 + Pe + splitA] = za.y;   // i=2l+1 uses interval 2l
    __syncwarp();

    // ---- coalesced float4 store ----
    const float4 q = ((const float4*)o)[lane];
    ((float4*)out_g)[(size_t)ray * 32 + lane] = q;
}

extern "C" void kernel_launch(void* const* d_in, const int* in_sizes, int n_in,
                              void* d_out, int out_size) {
    // metadata order: origins, directions, lengths, xys, ray_weights
    const float* lengths = (const float*)d_in[2];
    const float* weights = (const float*)d_in[4];
    float* out = (float*)d_out;
    refine_kernel<<<N_RAYS / WPB, THREADS>>>(lengths, weights, out);
}

// round 10
// speedup vs baseline: 1.1490x; 1.1490x over previous
#include <cuda_runtime.h>

// RayPointRefiner: inverse-CDF fine sampling + fully-analytic integer merge.
// N_RAYS=524288, N_PTS=64, N_FINE=64, out=[N_RAYS,128] sorted.
//
// One warp per ray; lane l owns cdf intervals A=2l, B=2l+1 and samples 2l,2l+1.
// u_k = k/63 uniform => interval boundaries t_j = ceil(63*cdf_j) (monotone by
// construction of the cdf). Divergent loops ONLY scatter interval ids
// inv[k]=m. Uniform phase: each lane interpolates its 2 samples from a
// per-interval quad (c, bin, dbin/denom, kstar). kstar = ceil(63*u*) where
// u* is the cdf height at the straddled coarse point z[m+1]; used as the single
// integer truth for both sample positions (k+m+1+(k>=kstar)) and coarse
// positions ((m+1)+kstar) => bijective tiling of [0,128), no sort needed.

#define EPSF 1e-5f

constexpr int N_RAYS  = 524288;
constexpr int WPB     = 8;
constexpr int THREADS = WPB * 32;
constexpr unsigned FULL = 0xffffffffu;
constexpr float INV63 = 1.0f / 63.0f;

__global__ __launch_bounds__(THREADS) void refine_kernel(
    const float* __restrict__ lengths,
    const float* __restrict__ rw,
    float* __restrict__ out_g)
{
    __shared__ __align__(16) float4 quad_sh[WPB][64];
    __shared__ __align__(8)  int    inv_sh [WPB][64];
    __shared__ __align__(16) float  o_sh   [WPB][128];
    const int lane = threadIdx.x & 31;
    const int warp = threadIdx.x >> 5;
    const int ray  = blockIdx.x * WPB + warp;
    float4* quad = quad_sh[warp];
    int*    inv  = inv_sh[warp];
    float*  o    = o_sh[warp];

    // ---- coalesced loads: lane l gets elements 2l, 2l+1 ----
    const float2 za = ((const float2*)lengths)[(size_t)ray * 32 + lane];
    const float2 wa = ((const float2*)rw)     [(size_t)ray * 32 + lane];

    const float znext = __shfl_down_sync(FULL, za.x, 1);   // z[2l+2]
    const float wnext = __shfl_down_sync(FULL, wa.x, 1);   // rw[2l+2]

    const float bin0 = 0.5f * (za.x + za.y);               // bins[2l]
    float       bin1 = 0.5f * (za.y + znext);              // bins[2l+1]
    float       binN = __shfl_down_sync(FULL, bin0, 1);    // bins[2l+2]

    // weights w[2l]=rw[2l+1]+eps, w[2l+1]=rw[2l+2]+eps (lanes 0..30)
    float w0 = 0.0f, w1 = 0.0f;
    if (lane < 31) { w0 = wa.y + EPSF; w1 = wnext + EPSF; }

    // inclusive warp scan of pair sums
    float incl = w0 + w1;
    #pragma unroll
    for (int d = 1; d < 32; d <<= 1) {
        float v = __shfl_up_sync(FULL, incl, d);
        if (lane >= d) incl += v;
    }
    float excl = __shfl_up_sync(FULL, incl, 1);
    if (lane == 0) excl = 0.0f;
    const float total = __shfl_sync(FULL, incl, 31);
    const float invW  = __fdividef(1.0f, total);

    // cdf boundaries owned by this lane (monotone by construction: nonneg adds,
    // same positive multiplier; adjacent lanes share bit-identical values).
    float c0 = excl * invW;              // cdf[2l]
    float c1 = (excl + w0) * invW;       // cdf[2l+1]
    float c2 = incl * invW;              // cdf[2l+2]
    if (lane == 30) c2 = 1.0f;           // exact top at cdf[62]
    if (lane == 31) { c0 = 1.0f; c1 = 1.0f; c2 = 1.0f; bin1 = bin0; binN = bin0; }

    // sample-count boundaries t_j = ceil(63*c_j); monotone since c monotone.
    int t1 = min(max((int)ceilf(c1 * 63.0f), 0), 64);
    int t2 = min(max((int)ceilf(c2 * 63.0f), 0), 64);
    if (lane == 31) { t1 = 64; t2 = 64; }        // synthetic interval 62 owns k=63
    int Pe = __shfl_up_sync(FULL, t2, 1);
    if (lane == 0) Pe = 0;
    t1 = max(t1, Pe);                            // provably no-op clamps
    t2 = max(t2, t1);

    // kstar: crossing index of straddled coarse point inside each interval
    const float dA = c1 - c0, dbA = bin1 - bin0;
    const float dB = c2 - c1, dbB = binN - bin1;
    const float uA = c0 + (za.y  - bin0) * __fdividef(dA, dbA);
    const float uB = c1 + (znext - bin1) * __fdividef(dB, dbB);
    int ksA = min(max((int)ceilf(uA * 63.0f), Pe), t1);
    int ksB = min(max((int)ceilf(uB * 63.0f), t1), t2);
    if (lane == 31) { ksA = 64; ksB = 64; }      // z[63] above everything

    // per-interval interpolation quads (reference denom<eps guard folded in)
    const float denA = (dA < EPSF) ? 1.0f : dA;
    const float denB = (dB < EPSF) ? 1.0f : dB;
    const float rdA  = __fdividef(dbA, denA);
    const float rdB  = __fdividef(dbB, denB);
    quad[2 * lane]     = make_float4(c0, bin0, rdA, __int_as_float(ksA));
    quad[2 * lane + 1] = make_float4(c1, bin1, rdB, __int_as_float(ksB));

    // divergent part: scatter interval ids only (1 STS per sample)
    for (int k = Pe; k < t1; ++k) inv[k] = 2 * lane;
    for (int k = t1; k < t2; ++k) inv[k] = 2 * lane + 1;
    __syncwarp();

    // ---- uniform sample phase: 2 samples per lane ----
    const int2 mm = ((const int2*)inv)[lane];
    #pragma unroll
    for (int q = 0; q < 2; q++) {
        const int k = 2 * lane + q;
        int m = q ? mm.y : mm.x;
        m = min(max(m, 0), 63);                          // OOB safety
        const float4 Q = quad[m];
        const float u = (k == 63) ? 1.0f : (float)k * INV63;
        const float z = fmaf(u - Q.x, Q.z, Q.y);
        const int ks  = __float_as_int(Q.w);
        const int pos = k + m + 1 + (k >= ks);
        o[pos] = z;
    }

    // ---- coarse placements (closed form) ----
    int pk = __shfl_up_sync(FULL, ksB, 1);               // kstar of interval 2l-1
    if (lane == 0) pk = 0;
    o[2 * lane + pk]      = za.x;                        // z[2l]
    o[2 * lane + 1 + ksA] = za.y;                        // z[2l+1]
    __syncwarp();

    // ---- coalesced float4 store ----
    const float4 r = ((const float4*)o)[lane];
    ((float4*)out_g)[(size_t)ray * 32 + lane] = r;
}

extern "C" void kernel_launch(void* const* d_in, const int* in_sizes, int n_in,
                              void* d_out, int out_size) {
    // metadata order: origins, directions, lengths, xys, ray_weights
    const float* lengths = (const float*)d_in[2];
    const float* weights = (const float*)d_in[4];
    float* out = (float*)d_out;
    refine_kernel<<<N_RAYS / WPB, THREADS>>>(lengths, weights, out);
}